// round 9
// baseline (speedup 1.0000x reference)
#include <cuda_runtime.h>

// out[b,d,t] = T*x[b,d,t] - 2 * sum_{s ≡ t (mod 2)} x[b,d,s],  T = 1024.
// (Dirichlet-kernel collapse of the rfft -> cos/sin GEMM reference; see R1.)
//
// R8: persistent warp-per-row with explicit software pipelining.
// Grid = 148 CTAs (one wave, 1 CTA/SM) x 8 warps; each warp iterates over
// rows with stride 1184, double-buffered: row i+1's loads are issued BEFORE
// row i's shuffle-reduce + store, so load latency is hidden behind
// independent work instead of occupancy. Streaming stores kept from R7.

#define ROW_LEN      1024
#define THREADS      256
#define WARPS_PER_CTA 8
#define GRID_CTAS    148
#define VEC_PER_LANE 8            // 8 float4 = 32 floats per lane

__device__ __forceinline__ void load_row(float4 v[VEC_PER_LANE],
                                         const float* __restrict__ x,
                                         long long row, int lane) {
    const float4* __restrict__ xr =
        reinterpret_cast<const float4*>(x + row * ROW_LEN);
    #pragma unroll
    for (int j = 0; j < VEC_PER_LANE; j++)
        v[j] = xr[lane + 32 * j];
}

__device__ __forceinline__ void reduce_store(const float4 v[VEC_PER_LANE],
                                             float* __restrict__ out,
                                             long long row, int lane) {
    // Element index of v[j].x is 4*(lane+32j): .x/.z even, .y/.w odd.
    float esum = 0.0f, osum = 0.0f;
    #pragma unroll
    for (int j = 0; j < VEC_PER_LANE; j++) {
        esum += v[j].x + v[j].z;
        osum += v[j].y + v[j].w;
    }
    #pragma unroll
    for (int off = 16; off > 0; off >>= 1) {
        esum += __shfl_xor_sync(0xffffffffu, esum, off);
        osum += __shfl_xor_sync(0xffffffffu, osum, off);
    }
    const float E2 = 2.0f * esum;
    const float O2 = 2.0f * osum;
    const float T  = (float)ROW_LEN;

    float4* __restrict__ outr = reinterpret_cast<float4*>(out + row * ROW_LEN);
    #pragma unroll
    for (int j = 0; j < VEC_PER_LANE; j++) {
        float4 r;
        r.x = fmaf(T, v[j].x, -E2);
        r.y = fmaf(T, v[j].y, -O2);
        r.z = fmaf(T, v[j].z, -E2);
        r.w = fmaf(T, v[j].w, -O2);
        __stcs(&outr[lane + 32 * j], r);
    }
}

__global__ __launch_bounds__(THREADS)
void season_block_46428596469890_kernel(const float* __restrict__ x,
                                        float* __restrict__ out, int n_rows) {
    const int lane = threadIdx.x & 31;
    const int warp = threadIdx.x >> 5;
    const int stride = GRID_CTAS * WARPS_PER_CTA;     // 1184
    long long row = (long long)blockIdx.x * WARPS_PER_CTA + warp;
    if (row >= n_rows) return;

    float4 va[VEC_PER_LANE], vb[VEC_PER_LANE];
    load_row(va, x, row, lane);

    for (;;) {
        long long n1 = row + stride;
        if (n1 < n_rows) load_row(vb, x, n1, lane);   // prefetch before reduce
        reduce_store(va, out, row, lane);
        if (n1 >= n_rows) break;

        long long n2 = n1 + stride;
        if (n2 < n_rows) load_row(va, x, n2, lane);   // prefetch before reduce
        reduce_store(vb, out, n1, lane);
        if (n2 >= n_rows) break;
        row = n2;
    }
}

extern "C" void kernel_launch(void* const* d_in, const int* in_sizes, int n_in,
                              void* d_out, int out_size) {
    const float* x = (const float*)d_in[0];
    float* out = (float*)d_out;
    const int n_rows = in_sizes[0] / ROW_LEN;         // 8192
    season_block_46428596469890_kernel<<<GRID_CTAS, THREADS>>>(x, out, n_rows);
}